// round 15
// baseline (speedup 1.0000x reference)
#include <cuda_runtime.h>
#include <cstdint>

// Problem constants
#define Bc 4
#define Nc 100
#define Cc 81
#define Mc 20
#define Lc 65536
#define LSEG 64
#define SEGLEN (Lc / LSEG)    // 1024
#define KCH 64                // K per chunk (bf16 SW128 row = 128B)
#define NCHUNK (SEGLEN / KCH) // 16
#define TPB 256

// g_pt: atomic-accumulated; combine consumes-and-clears each element, so every
// run (first run via BSS zero-init, later runs via prior combine) starts at 0.
// sp/st: per-z partial stores, written unconditionally -> never need zeroing.
// g_cnt: per-batch release counters; combine resets after consuming.
__device__ float g_pt[Bc * Nc * Mc];
__device__ float g_sp_part[LSEG * Bc * Nc];
__device__ float g_st_part[LSEG * Bc * Mc];
__device__ unsigned g_cnt[Bc];

// sigmoid(x) = 0.5*tanh(x/2) + 0.5  (1 MUFU)
__device__ __forceinline__ float fsigmoid(float x) {
    float t;
    asm("tanh.approx.f32 %0, %1;" : "=f"(t) : "f"(x * 0.5f));
    return fmaf(0.5f, t, 0.5f);
}
__device__ __forceinline__ uint32_t smem_u32(const void* p) {
    uint32_t a;
    asm("{ .reg .u64 t; cvta.to.shared.u64 t, %1; cvt.u32.u64 %0, t; }"
        : "=r"(a) : "l"(p));
    return a;
}
__device__ __forceinline__ uint32_t sw128(uint32_t off) {
    return off ^ ((off >> 3) & 0x70);
}
__device__ __forceinline__ void ldmx4(uint32_t addr, uint32_t& r0, uint32_t& r1,
                                      uint32_t& r2, uint32_t& r3) {
    asm volatile("ldmatrix.sync.aligned.m8n8.x4.shared.b16 {%0,%1,%2,%3}, [%4];"
                 : "=r"(r0), "=r"(r1), "=r"(r2), "=r"(r3) : "r"(addr));
}
__device__ __forceinline__ void ldmx2(uint32_t addr, uint32_t& r0, uint32_t& r1) {
    asm volatile("ldmatrix.sync.aligned.m8n8.x2.shared.b16 {%0,%1}, [%2];"
                 : "=r"(r0), "=r"(r1) : "r"(addr));
}
__device__ __forceinline__ void mma16816(float* c, const uint32_t* a, uint32_t b0,
                                         uint32_t b1) {
    asm volatile(
        "mma.sync.aligned.m16n8k16.row.col.f32.bf16.bf16.f32 "
        "{%0,%1,%2,%3}, {%4,%5,%6,%7}, {%8,%9}, {%0,%1,%2,%3};"
        : "+f"(c[0]), "+f"(c[1]), "+f"(c[2]), "+f"(c[3])
        : "r"(a[0]), "r"(a[1]), "r"(a[2]), "r"(a[3]), "r"(b0), "r"(b1));
}
__device__ __forceinline__ uint32_t packbf(float lo, float hi) {
    uint32_t r;
    asm("cvt.rn.satfinite.bf16x2.f32 %0, %1, %2;" : "=r"(r) : "f"(hi), "f"(lo));
    return r;
}

// Combine, executed by 4 dedicated blocks (one per batch). __noinline__
// isolates its register allocation from the main loop (R11 lesson).
__device__ __noinline__ void combine_block(int b, const float* logits,
                                           const int* labels, float* out) {
    __shared__ float s_sp[Nc];
    __shared__ float s_st[Mc];
    const int tid = threadIdx.x;

    // Spin until all 64 main blocks of this batch have released.
    if (tid == 0) {
        unsigned v;
        do {
            asm volatile("ld.acquire.gpu.u32 %0, [%1];"
                         : "=r"(v) : "l"(&g_cnt[b]) : "memory");
            if (v < LSEG) __nanosleep(128);
        } while (v < LSEG);
    }
    __syncthreads(); // tid0's acquire + barrier orders subsequent loads

    // Phase 1: reduce sp (100 rows) + st (20) over 64 z partials.
    if (tid < Nc) {
        float s = 0.f;
#pragma unroll 8
        for (int z = 0; z < LSEG; z++) s += g_sp_part[(z * Bc + b) * Nc + tid];
        s_sp[tid] = s;
    } else if (tid < Nc + Mc) {
        const int m = tid - Nc;
        float s = 0.f;
#pragma unroll 8
        for (int z = 0; z < LSEG; z++) s += g_st_part[(z * Bc + b) * Mc + m];
        s_st[m] = s;
    }
    __syncthreads();

    // Phase 2: 2000 outputs; consume-and-clear g_pt for the next replay.
    // gt_labels is int32 (JAX x64-disabled); clamp so bad labels can't trap.
    const float invL = 1.0f / (float)Lc;
    for (int i = tid; i < Nc * Mc; i += TPB) {
        const int n = i / Mc, m = i % Mc;
        const int o = (b * Nc + n) * Mc + m;
        float pt = g_pt[o];
        g_pt[o] = 0.f;
        float sp = s_sp[n];
        float st = s_st[m];
        int lab = labels[b * Mc + m];
        lab = lab < 0 ? 0 : (lab >= Cc ? Cc - 1 : lab);
        float logit = logits[(b * Nc + n) * Cc + lab];
        float cost_class = -logit;
        float cost_mask = -(2.0f * pt + (float)Lc - sp - st) * invL;
        float cost_dice = 1.0f - (2.0f * pt + 1.0f) / (sp + st + 1.0f);
        out[o] = cost_class + cost_mask + cost_dice;
    }
    __syncthreads();
    if (tid == 0) g_cnt[b] = 0; // reset for next replay (sole consumer)
}

__global__ void __launch_bounds__(TPB, 2) main_kernel(
    const float* __restrict__ pm, const float* __restrict__ gt,
    const float* __restrict__ logits, const int* __restrict__ labels,
    float* __restrict__ out) {
    __shared__ __align__(128) char pbf[2][16384]; // p bf16: 128 rows x 128B
    __shared__ __align__(128) char tbf[2][4096];  // t bf16: 32 rows x 128B

    const int tid = threadIdx.x, wid = tid >> 5, lane = tid & 31;
    const int z = blockIdx.x, b = blockIdx.y;

    // Dedicated combine blocks (x == LSEG) take a disjoint early path.
    if (z == LSEG) {
        combine_block(b, logits, labels, out);
        return;
    }

    const float* pmb = pm + (size_t)(b * Nc) * Lc + z * SEGLEN;
    const float* gtb = gt + (size_t)(b * Mc) * Lc + z * SEGLEN;

    // Zero t pad rows 20-31 (both buffers) — covered by the chunk-0 sync.
    {
        uint4 zz = {0, 0, 0, 0};
        for (int i = tid; i < 2 * 1536 / 16; i += TPB) {
            int bi = i < 96 ? 0 : 1;
            int off = (i - bi * 96) * 16;
            *(uint4*)(&tbf[bi][2560 + off]) = zz;
        }
    }

    // Per-lane ldmatrix address components. Swizzle decomposition:
    //   sw128(row*128 + kb) = row*128 + (kb ^ ((row&7)<<4)) for kb in [0,128)
    const int lr = lane & 7;
    const int a_row = 16 * wid + ((lane >> 3) & 1) * 8 + lr;
    const uint32_t a_base = (uint32_t)a_row * 128;
    const uint32_t a_x = (uint32_t)(a_row & 7) << 4;
    const uint32_t a_kb = ((lane >> 4) & 1) * 16;
    const int b01_row = ((lane >> 4) & 1) * 8 + lr;
    const uint32_t b01_base = (uint32_t)b01_row * 128;
    const uint32_t b01_x = (uint32_t)(b01_row & 7) << 4;
    const uint32_t b01_kb = ((lane >> 3) & 1) * 16;
    const int b2_row = 16 + lr;
    const uint32_t b2_base = (uint32_t)b2_row * 128;
    const uint32_t b2_x = (uint32_t)(b2_row & 7) << 4;
    const uint32_t b2_kb = ((lane >> 3) & 1) * 16;

    float acc[3][4];
#pragma unroll
    for (int j = 0; j < 3; j++)
#pragma unroll
        for (int q = 0; q < 4; q++) acc[j][q] = 0.f;
    float sp_loc[7] = {0, 0, 0, 0, 0, 0, 0};
    float st0 = 0.f, st1 = 0.f;

    float4 pr[7], tr0, tr1;
    // Load chunk 0
#pragma unroll
    for (int k = 0; k < 7; k++) {
        int j = tid + k * TPB;
        if (j < 1600) {
            int row = j >> 4, cc = j & 15;
            pr[k] = __ldcs((const float4*)(pmb + (size_t)row * Lc) + cc);
        }
    }
    {
        int row = tid >> 4, cc = tid & 15;
        tr0 = __ldcs((const float4*)(gtb + (size_t)row * Lc) + cc);
        if (tid < 64)
            tr1 = __ldcs((const float4*)(gtb + (size_t)(16 + row) * Lc) + cc);
    }

    for (int c = 0; c < NCHUNK; c++) {
        const int buf = c & 1;
        // Convert chunk c from registers -> bf16 smem (swizzled)
#pragma unroll
        for (int k = 0; k < 7; k++) {
            int j = tid + k * TPB;
            if (j < 1600) {
                int row = j >> 4, cc = j & 15;
                float s0 = fsigmoid(pr[k].x), s1 = fsigmoid(pr[k].y);
                float s2 = fsigmoid(pr[k].z), s3 = fsigmoid(pr[k].w);
                sp_loc[k] += (s0 + s1) + (s2 + s3);
                uint2 w = {packbf(s0, s1), packbf(s2, s3)};
                *(uint2*)(&pbf[buf][sw128((uint32_t)(row * 128 + cc * 8))]) = w;
            }
        }
        {
            int row = tid >> 4, cc = tid & 15;
            st0 += (tr0.x + tr0.y) + (tr0.z + tr0.w);
            uint2 w = {packbf(tr0.x, tr0.y), packbf(tr0.z, tr0.w)};
            *(uint2*)(&tbf[buf][sw128((uint32_t)(row * 128 + cc * 8))]) = w;
            if (tid < 64) {
                st1 += (tr1.x + tr1.y) + (tr1.z + tr1.w);
                uint2 w2 = {packbf(tr1.x, tr1.y), packbf(tr1.z, tr1.w)};
                *(uint2*)(&tbf[buf][sw128((uint32_t)((16 + row) * 128 + cc * 8))]) = w2;
            }
        }
        // Issue loads for chunk c+1 (latency hidden behind sync + MMA)
        if (c + 1 < NCHUNK) {
            const int c1 = (c + 1) * KCH;
#pragma unroll
            for (int k = 0; k < 7; k++) {
                int j = tid + k * TPB;
                if (j < 1600) {
                    int row = j >> 4, cc = j & 15;
                    pr[k] = __ldcs((const float4*)(pmb + (size_t)row * Lc + c1) + cc);
                }
            }
            int row = tid >> 4, cc = tid & 15;
            tr0 = __ldcs((const float4*)(gtb + (size_t)row * Lc + c1) + cc);
            if (tid < 64)
                tr1 = __ldcs((const float4*)(gtb + (size_t)(16 + row) * Lc + c1) + cc);
        }
        __syncthreads(); // bf16[buf] ready; also fences prior MMA reads of buf

        // Warp-level GEMM on bf16[buf]: 4 k16-steps
        const uint32_t pb = smem_u32(&pbf[buf][0]);
        const uint32_t tb = smem_u32(&tbf[buf][0]);
#pragma unroll
        for (int ks = 0; ks < 4; ks++) {
            const uint32_t kb = (uint32_t)ks * 32;
            uint32_t a[4], b0[2], b1[2], b2r[2];
            ldmx4(pb + a_base + ((a_kb + kb) ^ a_x), a[0], a[1], a[2], a[3]);
            ldmx4(tb + b01_base + ((b01_kb + kb) ^ b01_x), b0[0], b0[1], b1[0], b1[1]);
            ldmx2(tb + b2_base + ((b2_kb + kb) ^ b2_x), b2r[0], b2r[1]);
            mma16816(acc[0], a, b0[0], b0[1]);
            mma16816(acc[1], a, b1[0], b1[1]);
            mma16816(acc[2], a, b2r[0], b2r[1]);
        }
    }

    // ---- Epilogue: pt via atomics; sp/st via per-z partial stores ----
    {
        const int gr = lane >> 2, qc = lane & 3;
        const int r0 = 16 * wid + gr, r1 = r0 + 8;
#pragma unroll
        for (int j = 0; j < 3; j++) {
            int col = 8 * j + 2 * qc;
            if (col + 1 < Mc) {
                if (r0 < Nc) {
                    atomicAdd(&g_pt[(b * Nc + r0) * Mc + col], acc[j][0]);
                    atomicAdd(&g_pt[(b * Nc + r0) * Mc + col + 1], acc[j][1]);
                }
                if (r1 < Nc) {
                    atomicAdd(&g_pt[(b * Nc + r1) * Mc + col], acc[j][2]);
                    atomicAdd(&g_pt[(b * Nc + r1) * Mc + col + 1], acc[j][3]);
                }
            }
        }
    }
    // sp: 16-lane groups share a p-row; plain store to this block's z-slot
#pragma unroll
    for (int k = 0; k < 7; k++) {
        float v = sp_loc[k];
#pragma unroll
        for (int o = 8; o; o >>= 1) v += __shfl_down_sync(0xffffffffu, v, o, 16);
        int row = (tid + k * TPB) >> 4;
        if ((lane & 15) == 0 && row < Nc)
            g_sp_part[(z * Bc + b) * Nc + row] = v;
    }
    // st
    {
        float v = st0;
#pragma unroll
        for (int o = 8; o; o >>= 1) v += __shfl_down_sync(0xffffffffu, v, o, 16);
        if ((lane & 15) == 0) g_st_part[(z * Bc + b) * Mc + (tid >> 4)] = v;
        float u = st1;
#pragma unroll
        for (int o = 8; o; o >>= 1) u += __shfl_down_sync(0xffffffffu, u, o, 16);
        if ((lane & 15) == 0 && tid < 64)
            g_st_part[(z * Bc + b) * Mc + 16 + (tid >> 4)] = u;
    }

    // Release: publish stores, then bump this batch's counter.
    __threadfence();
    __syncthreads();
    if (tid == 0) atomicAdd(&g_cnt[b], 1u);
}

extern "C" void kernel_launch(void* const* d_in, const int* in_sizes, int n_in,
                              void* d_out, int out_size) {
    const float* pred_logits = (const float*)d_in[0]; // (4,100,81) f32
    const float* pred_masks = (const float*)d_in[1];  // (4,100,256,256) f32
    const int* gt_labels = (const int*)d_in[2];       // (4,20) int32
    const float* gt_masks = (const float*)d_in[3];    // (4,20,256,256) f32
    float* out = (float*)d_out;                       // (4,100,20) f32

    dim3 grid(LSEG + 1, Bc); // 256 main blocks + 4 combine blocks (all resident)
    main_kernel<<<grid, TPB>>>(pred_masks, gt_masks, pred_logits, gt_labels, out);
}

// round 16
// speedup vs baseline: 1.2497x; 1.2497x over previous
#include <cuda_runtime.h>
#include <cstdint>

// Problem constants
#define Bc 4
#define Nc 100
#define Cc 81
#define Mc 20
#define Lc 65536
#define LSEG 64
#define SEGLEN (Lc / LSEG)    // 1024
#define KCH 64                // K per chunk (bf16 SW128 row = 128B)
#define NCHUNK (SEGLEN / KCH) // 16
#define TPB 256

// Dynamic smem layout (bytes)
#define SM_PBF 0              // p bf16: 2 x 16384 (128 rows x 128B)
#define SM_TBF 32768          // t bf16: 2 x 4096  (32 rows x 128B)
#define SM_PRAW 40960         // p raw fp32: 2 x 25600 (100 rows x 256B)
#define SM_TRAW 92160         // t raw fp32: 2 x 5120  (20 rows x 256B)
#define SMEM_TOTAL 102400

// g_pt: atomic-accumulated; combine consumes-and-clears each element.
// sp/st: per-z partial stores, written unconditionally -> never need zeroing.
__device__ float g_pt[Bc * Nc * Mc];
__device__ float g_sp_part[LSEG * Bc * Nc];
__device__ float g_st_part[LSEG * Bc * Mc];

// sigmoid(x) = 0.5*tanh(x/2) + 0.5  (1 MUFU)
__device__ __forceinline__ float fsigmoid(float x) {
    float t;
    asm("tanh.approx.f32 %0, %1;" : "=f"(t) : "f"(x * 0.5f));
    return fmaf(0.5f, t, 0.5f);
}
__device__ __forceinline__ uint32_t smem_u32(const void* p) {
    uint32_t a;
    asm("{ .reg .u64 t; cvta.to.shared.u64 t, %1; cvt.u32.u64 %0, t; }"
        : "=r"(a) : "l"(p));
    return a;
}
__device__ __forceinline__ uint32_t sw128(uint32_t off) {
    return off ^ ((off >> 3) & 0x70);
}
__device__ __forceinline__ void cp16cg(uint32_t dst, const void* src) {
    asm volatile("cp.async.cg.shared.global [%0], [%1], 16;"
                 :: "r"(dst), "l"(src) : "memory");
}
__device__ __forceinline__ void ldmx4(uint32_t addr, uint32_t& r0, uint32_t& r1,
                                      uint32_t& r2, uint32_t& r3) {
    asm volatile("ldmatrix.sync.aligned.m8n8.x4.shared.b16 {%0,%1,%2,%3}, [%4];"
                 : "=r"(r0), "=r"(r1), "=r"(r2), "=r"(r3) : "r"(addr));
}
__device__ __forceinline__ void ldmx2(uint32_t addr, uint32_t& r0, uint32_t& r1) {
    asm volatile("ldmatrix.sync.aligned.m8n8.x2.shared.b16 {%0,%1}, [%2];"
                 : "=r"(r0), "=r"(r1) : "r"(addr));
}
__device__ __forceinline__ void mma16816(float* c, const uint32_t* a, uint32_t b0,
                                         uint32_t b1) {
    asm volatile(
        "mma.sync.aligned.m16n8k16.row.col.f32.bf16.bf16.f32 "
        "{%0,%1,%2,%3}, {%4,%5,%6,%7}, {%8,%9}, {%0,%1,%2,%3};"
        : "+f"(c[0]), "+f"(c[1]), "+f"(c[2]), "+f"(c[3])
        : "r"(a[0]), "r"(a[1]), "r"(a[2]), "r"(a[3]), "r"(b0), "r"(b1));
}
__device__ __forceinline__ uint32_t packbf(float lo, float hi) {
    uint32_t r;
    asm("cvt.rn.satfinite.bf16x2.f32 %0, %1, %2;" : "=r"(r) : "f"(hi), "f"(lo));
    return r;
}

// Issue cp.async loads for chunk c into raw[c&1]. Each thread copies exactly
// the cells it later converts -> wait_group alone orders cp->convert.
__device__ __forceinline__ void issue_chunk(uint32_t sb, const float* pmb,
                                            const float* gtb, int c, int tid) {
    const int buf = c & 1;
    const uint32_t pr = sb + SM_PRAW + buf * 25600;
    const uint32_t tr = sb + SM_TRAW + buf * 5120;
    const int c0 = c * KCH;
#pragma unroll
    for (int k = 0; k < 7; k++) {
        int j = tid + k * TPB;
        if (j < 1600) {
            int row = j >> 4, cc = j & 15;
            cp16cg(pr + row * 256 + cc * 16, pmb + (size_t)row * Lc + c0 + cc * 4);
        }
    }
    {
        int row = tid >> 4, cc = tid & 15;
        cp16cg(tr + row * 256 + cc * 16, gtb + (size_t)row * Lc + c0 + cc * 4);
        if (tid < 64)
            cp16cg(tr + (16 + row) * 256 + cc * 16,
                   gtb + (size_t)(16 + row) * Lc + c0 + cc * 4);
    }
    asm volatile("cp.async.commit_group;" ::: "memory");
}

__global__ void __launch_bounds__(TPB, 2) main_kernel(const float* __restrict__ pm,
                                                      const float* __restrict__ gt) {
    extern __shared__ __align__(128) char smem[];
    const uint32_t sb = smem_u32(smem);
    const int tid = threadIdx.x, wid = tid >> 5, lane = tid & 31;
    const int z = blockIdx.x, b = blockIdx.y;
    const float* pmb = pm + (size_t)(b * Nc) * Lc + z * SEGLEN;
    const float* gtb = gt + (size_t)(b * Mc) * Lc + z * SEGLEN;

    // Zero t bf16 pad rows 20-31 (both buffers) — covered by chunk-0 sync.
    {
        uint4 zz = {0, 0, 0, 0};
        for (int i = tid; i < 2 * 1536 / 16; i += TPB) {
            int bi = i < 96 ? 0 : 1;
            int off = (i - bi * 96) * 16;
            *(uint4*)(smem + SM_TBF + bi * 4096 + 2560 + off) = zz;
        }
    }

    // Per-lane ldmatrix address components. Swizzle decomposition:
    //   sw128(row*128 + kb) = row*128 + (kb ^ ((row&7)<<4)) for kb in [0,128)
    const int lr = lane & 7;
    const int a_row = 16 * wid + ((lane >> 3) & 1) * 8 + lr;
    const uint32_t a_base = (uint32_t)a_row * 128;
    const uint32_t a_x = (uint32_t)(a_row & 7) << 4;
    const uint32_t a_kb = ((lane >> 4) & 1) * 16;
    const int b01_row = ((lane >> 4) & 1) * 8 + lr;
    const uint32_t b01_base = (uint32_t)b01_row * 128;
    const uint32_t b01_x = (uint32_t)(b01_row & 7) << 4;
    const uint32_t b01_kb = ((lane >> 3) & 1) * 16;
    const int b2_row = 16 + lr;
    const uint32_t b2_base = (uint32_t)b2_row * 128;
    const uint32_t b2_x = (uint32_t)(b2_row & 7) << 4;
    const uint32_t b2_kb = ((lane >> 3) & 1) * 16;

    float acc[3][4];
#pragma unroll
    for (int j = 0; j < 3; j++)
#pragma unroll
        for (int q = 0; q < 4; q++) acc[j][q] = 0.f;
    float sp_loc[7] = {0, 0, 0, 0, 0, 0, 0};
    float st0 = 0.f, st1 = 0.f;

    // Prologue: prefetch chunks 0 and 1 (prefetch distance 2)
    issue_chunk(sb, pmb, gtb, 0, tid);
    issue_chunk(sb, pmb, gtb, 1, tid);

    for (int c = 0; c < NCHUNK; c++) {
        const int buf = c & 1;
        // Wait for chunk c (leave chunk c+1 in flight)
        if (c + 1 < NCHUNK)
            asm volatile("cp.async.wait_group 1;" ::: "memory");
        else
            asm volatile("cp.async.wait_group 0;" ::: "memory");

        // Convert p: raw fp32 -> sigmoid -> bf16x2 swizzled
        const char* praw = smem + SM_PRAW + buf * 25600;
        char* pbf = smem + SM_PBF + buf * 16384;
#pragma unroll
        for (int k = 0; k < 7; k++) {
            int j = tid + k * TPB;
            if (j < 1600) {
                int row = j >> 4, cc = j & 15;
                float4 v = *(const float4*)(praw + row * 256 + cc * 16);
                float s0 = fsigmoid(v.x), s1 = fsigmoid(v.y);
                float s2 = fsigmoid(v.z), s3 = fsigmoid(v.w);
                sp_loc[k] += (s0 + s1) + (s2 + s3);
                uint2 w = {packbf(s0, s1), packbf(s2, s3)};
                *(uint2*)(&pbf[sw128((uint32_t)(row * 128 + cc * 8))]) = w;
            }
        }
        // Convert t (rows 0..19)
        {
            const char* traw = smem + SM_TRAW + buf * 5120;
            char* tbf = smem + SM_TBF + buf * 4096;
            int row = tid >> 4, cc = tid & 15;
            float4 v = *(const float4*)(traw + row * 256 + cc * 16);
            st0 += (v.x + v.y) + (v.z + v.w);
            uint2 w = {packbf(v.x, v.y), packbf(v.z, v.w)};
            *(uint2*)(&tbf[sw128((uint32_t)(row * 128 + cc * 8))]) = w;
            if (tid < 64) {
                float4 u = *(const float4*)(traw + (16 + row) * 256 + cc * 16);
                st1 += (u.x + u.y) + (u.z + u.w);
                uint2 w2 = {packbf(u.x, u.y), packbf(u.z, u.w)};
                *(uint2*)(&tbf[sw128((uint32_t)((16 + row) * 128 + cc * 8))]) = w2;
            }
        }
        // raw[buf] now free (this thread read its own cells): prefetch c+2
        if (c + 2 < NCHUNK) issue_chunk(sb, pmb, gtb, c + 2, tid);

        __syncthreads(); // bf16[buf] ready; all threads past MMA(c-2)

        // Warp-level GEMM on bf16[buf]: 4 k16-steps
        const uint32_t pb = sb + SM_PBF + buf * 16384;
        const uint32_t tb = sb + SM_TBF + buf * 4096;
#pragma unroll
        for (int ks = 0; ks < 4; ks++) {
            const uint32_t kb = (uint32_t)ks * 32;
            uint32_t a[4], b0[2], b1[2], b2r[2];
            ldmx4(pb + a_base + ((a_kb + kb) ^ a_x), a[0], a[1], a[2], a[3]);
            ldmx4(tb + b01_base + ((b01_kb + kb) ^ b01_x), b0[0], b0[1], b1[0], b1[1]);
            ldmx2(tb + b2_base + ((b2_kb + kb) ^ b2_x), b2r[0], b2r[1]);
            mma16816(acc[0], a, b0[0], b0[1]);
            mma16816(acc[1], a, b1[0], b1[1]);
            mma16816(acc[2], a, b2r[0], b2r[1]);
        }
    }

    // ---- Epilogue: pt via atomics; sp/st via per-z partial stores ----
    {
        const int gr = lane >> 2, qc = lane & 3;
        const int r0 = 16 * wid + gr, r1 = r0 + 8;
#pragma unroll
        for (int j = 0; j < 3; j++) {
            int col = 8 * j + 2 * qc;
            if (col + 1 < Mc) {
                if (r0 < Nc) {
                    atomicAdd(&g_pt[(b * Nc + r0) * Mc + col], acc[j][0]);
                    atomicAdd(&g_pt[(b * Nc + r0) * Mc + col + 1], acc[j][1]);
                }
                if (r1 < Nc) {
                    atomicAdd(&g_pt[(b * Nc + r1) * Mc + col], acc[j][2]);
                    atomicAdd(&g_pt[(b * Nc + r1) * Mc + col + 1], acc[j][3]);
                }
            }
        }
    }
    // sp: 16-lane groups share a p-row; plain store to this block's z-slot
#pragma unroll
    for (int k = 0; k < 7; k++) {
        float v = sp_loc[k];
#pragma unroll
        for (int o = 8; o; o >>= 1) v += __shfl_down_sync(0xffffffffu, v, o, 16);
        int row = (tid + k * TPB) >> 4;
        if ((lane & 15) == 0 && row < Nc)
            g_sp_part[(z * Bc + b) * Nc + row] = v;
    }
    // st
    {
        float v = st0;
#pragma unroll
        for (int o = 8; o; o >>= 1) v += __shfl_down_sync(0xffffffffu, v, o, 16);
        if ((lane & 15) == 0) g_st_part[(z * Bc + b) * Mc + (tid >> 4)] = v;
        float u = st1;
#pragma unroll
        for (int o = 8; o; o >>= 1) u += __shfl_down_sync(0xffffffffu, u, o, 16);
        if ((lane & 15) == 0 && tid < 64)
            g_st_part[(z * Bc + b) * Mc + 16 + (tid >> 4)] = u;
    }
}

// Combine (R13 version — two-launch tail is the proven best).
// gt_labels is int32 (JAX x64-disabled); clamp so bad labels can't trap.
__global__ void combine_kernel(const float* __restrict__ logits,
                               const int* __restrict__ labels,
                               float* __restrict__ out) {
    __shared__ float s_sp[10];
    __shared__ float s_st[Mc];
    const int tid = threadIdx.x;
    const int g0 = blockIdx.x * 10;
    const int b = g0 / Nc, n0 = g0 % Nc;

    // Phase 1: 32 keys (30 real), all threads execute the shfl.
    {
        const int key = tid >> 3, sub = tid & 7;
        float s = 0.f;
        if (key < 10) {
#pragma unroll
            for (int i = 0; i < 8; i++)
                s += g_sp_part[((sub + 8 * i) * Bc + b) * Nc + n0 + key];
        } else if (key < 30) {
#pragma unroll
            for (int i = 0; i < 8; i++)
                s += g_st_part[((sub + 8 * i) * Bc + b) * Mc + (key - 10)];
        }
#pragma unroll
        for (int o2 = 4; o2; o2 >>= 1) s += __shfl_down_sync(0xffffffffu, s, o2, 8);
        if (sub == 0 && key < 30) {
            if (key < 10) s_sp[key] = s;
            else s_st[key - 10] = s;
        }
    }
    __syncthreads();

    // Phase 2: 200 outputs; consume-and-clear g_pt for the next replay.
    if (tid < 200) {
        const int o = g0 * Mc + tid;
        const int m = tid % Mc, ng = tid / Mc;
        float pt = g_pt[o];
        g_pt[o] = 0.f;
        float sp = s_sp[ng];
        float st = s_st[m];
        int lab = labels[b * Mc + m];
        lab = lab < 0 ? 0 : (lab >= Cc ? Cc - 1 : lab);
        float logit = logits[(b * Nc + n0 + ng) * Cc + lab];

        const float invL = 1.0f / (float)Lc;
        float cost_class = -logit;
        float cost_mask = -(2.0f * pt + (float)Lc - sp - st) * invL;
        float cost_dice = 1.0f - (2.0f * pt + 1.0f) / (sp + st + 1.0f);
        out[o] = cost_class + cost_mask + cost_dice;
    }
}

extern "C" void kernel_launch(void* const* d_in, const int* in_sizes, int n_in,
                              void* d_out, int out_size) {
    const float* pred_logits = (const float*)d_in[0]; // (4,100,81) f32
    const float* pred_masks = (const float*)d_in[1];  // (4,100,256,256) f32
    const int* gt_labels = (const int*)d_in[2];       // (4,20) int32
    const float* gt_masks = (const float*)d_in[3];    // (4,20,256,256) f32
    float* out = (float*)d_out;                       // (4,100,20) f32

    static bool attr_set = false;
    if (!attr_set) {
        cudaFuncSetAttribute(main_kernel, cudaFuncAttributeMaxDynamicSharedMemorySize,
                             SMEM_TOTAL);
        attr_set = true;
    }
    dim3 grid(LSEG, Bc);
    main_kernel<<<grid, TPB, SMEM_TOTAL>>>(pred_masks, gt_masks);
    combine_kernel<<<Bc * Nc / 10, 256>>>(pred_logits, gt_labels, out);
}

// round 17
// speedup vs baseline: 1.2823x; 1.0260x over previous
#include <cuda_runtime.h>
#include <cstdint>

// Problem constants
#define Bc 4
#define Nc 100
#define Cc 81
#define Mc 20
#define Lc 65536
#define KCH 64                 // K per chunk (bf16 SW128 row = 128B)
#define CHUNKS_PER_B (Lc / KCH) // 1024
#define ZB 74                  // z-blocks per batch: 62x14 + 12x13 = 1024 chunks
#define TPB 256

// g_pt: atomic-accumulated; combine consumes-and-clears each element, so every
// run (first run via BSS zero-init, later via prior combine) starts at 0.
// sp/st: per-z partial stores, written unconditionally -> never need zeroing.
__device__ float g_pt[Bc * Nc * Mc];
__device__ float g_sp_part[ZB * Bc * Nc];
__device__ float g_st_part[ZB * Bc * Mc];

// sigmoid(x) = 0.5*tanh(x/2) + 0.5  (1 MUFU)
__device__ __forceinline__ float fsigmoid(float x) {
    float t;
    asm("tanh.approx.f32 %0, %1;" : "=f"(t) : "f"(x * 0.5f));
    return fmaf(0.5f, t, 0.5f);
}
__device__ __forceinline__ uint32_t smem_u32(const void* p) {
    uint32_t a;
    asm("{ .reg .u64 t; cvta.to.shared.u64 t, %1; cvt.u32.u64 %0, t; }"
        : "=r"(a) : "l"(p));
    return a;
}
__device__ __forceinline__ uint32_t sw128(uint32_t off) {
    return off ^ ((off >> 3) & 0x70);
}
__device__ __forceinline__ void ldmx4(uint32_t addr, uint32_t& r0, uint32_t& r1,
                                      uint32_t& r2, uint32_t& r3) {
    asm volatile("ldmatrix.sync.aligned.m8n8.x4.shared.b16 {%0,%1,%2,%3}, [%4];"
                 : "=r"(r0), "=r"(r1), "=r"(r2), "=r"(r3) : "r"(addr));
}
__device__ __forceinline__ void ldmx2(uint32_t addr, uint32_t& r0, uint32_t& r1) {
    asm volatile("ldmatrix.sync.aligned.m8n8.x2.shared.b16 {%0,%1}, [%2];"
                 : "=r"(r0), "=r"(r1) : "r"(addr));
}
__device__ __forceinline__ void mma16816(float* c, const uint32_t* a, uint32_t b0,
                                         uint32_t b1) {
    asm volatile(
        "mma.sync.aligned.m16n8k16.row.col.f32.bf16.bf16.f32 "
        "{%0,%1,%2,%3}, {%4,%5,%6,%7}, {%8,%9}, {%0,%1,%2,%3};"
        : "+f"(c[0]), "+f"(c[1]), "+f"(c[2]), "+f"(c[3])
        : "r"(a[0]), "r"(a[1]), "r"(a[2]), "r"(a[3]), "r"(b0), "r"(b1));
}
__device__ __forceinline__ uint32_t packbf(float lo, float hi) {
    uint32_t r;
    asm("cvt.rn.satfinite.bf16x2.f32 %0, %1, %2;" : "=r"(r) : "f"(hi), "f"(lo));
    return r;
}

__global__ void __launch_bounds__(TPB, 2) main_kernel(const float* __restrict__ pm,
                                                      const float* __restrict__ gt) {
    __shared__ __align__(128) char pbf[2][16384]; // p bf16: 128 rows x 128B
    __shared__ __align__(128) char tbf[2][4096];  // t bf16: 32 rows x 128B

    const int tid = threadIdx.x, wid = tid >> 5, lane = tid & 31;
    const int z = blockIdx.x, b = blockIdx.y;

    // Chunk range for this block: blocks 0-61 take 14 chunks, 62-73 take 13.
    const int start = (z < 62) ? z * 14 : 868 + (z - 62) * 13;
    const int cend = start + ((z < 62) ? 14 : 13);

    const float* pmb = pm + (size_t)(b * Nc) * Lc;
    const float* gtb = gt + (size_t)(b * Mc) * Lc;

    // Zero t pad rows 20-31 (both buffers) — covered by the chunk-0 sync.
    {
        uint4 zz = {0, 0, 0, 0};
        for (int i = tid; i < 2 * 1536 / 16; i += TPB) {
            int bi = i < 96 ? 0 : 1;
            int off = (i - bi * 96) * 16;
            *(uint4*)(&tbf[bi][2560 + off]) = zz;
        }
    }

    // Per-lane ldmatrix address components. Swizzle decomposition:
    //   sw128(row*128 + kb) = row*128 + (kb ^ ((row&7)<<4)) for kb in [0,128)
    const int lr = lane & 7;
    const int a_row = 16 * wid + ((lane >> 3) & 1) * 8 + lr;
    const uint32_t a_base = (uint32_t)a_row * 128;
    const uint32_t a_x = (uint32_t)(a_row & 7) << 4;
    const uint32_t a_kb = ((lane >> 4) & 1) * 16;
    const int b01_row = ((lane >> 4) & 1) * 8 + lr;
    const uint32_t b01_base = (uint32_t)b01_row * 128;
    const uint32_t b01_x = (uint32_t)(b01_row & 7) << 4;
    const uint32_t b01_kb = ((lane >> 3) & 1) * 16;
    const int b2_row = 16 + lr;
    const uint32_t b2_base = (uint32_t)b2_row * 128;
    const uint32_t b2_x = (uint32_t)(b2_row & 7) << 4;
    const uint32_t b2_kb = ((lane >> 3) & 1) * 16;

    float acc[3][4];
#pragma unroll
    for (int j = 0; j < 3; j++)
#pragma unroll
        for (int q = 0; q < 4; q++) acc[j][q] = 0.f;
    float sp_loc[7] = {0, 0, 0, 0, 0, 0, 0};
    float st0 = 0.f, st1 = 0.f;

    float4 pr[7], tr0, tr1;
    // Load first chunk
    {
        const int c0 = start * KCH;
#pragma unroll
        for (int k = 0; k < 7; k++) {
            int j = tid + k * TPB;
            if (j < 1600) {
                int row = j >> 4, cc = j & 15;
                pr[k] = __ldcs((const float4*)(pmb + (size_t)row * Lc + c0) + cc);
            }
        }
        int row = tid >> 4, cc = tid & 15;
        tr0 = __ldcs((const float4*)(gtb + (size_t)row * Lc + c0) + cc);
        if (tid < 64)
            tr1 = __ldcs((const float4*)(gtb + (size_t)(16 + row) * Lc + c0) + cc);
    }

    for (int ch = start; ch < cend; ch++) {
        const int buf = ch & 1;
        // Convert chunk ch from registers -> bf16 smem (swizzled)
#pragma unroll
        for (int k = 0; k < 7; k++) {
            int j = tid + k * TPB;
            if (j < 1600) {
                int row = j >> 4, cc = j & 15;
                float s0 = fsigmoid(pr[k].x), s1 = fsigmoid(pr[k].y);
                float s2 = fsigmoid(pr[k].z), s3 = fsigmoid(pr[k].w);
                sp_loc[k] += (s0 + s1) + (s2 + s3);
                uint2 w = {packbf(s0, s1), packbf(s2, s3)};
                *(uint2*)(&pbf[buf][sw128((uint32_t)(row * 128 + cc * 8))]) = w;
            }
        }
        {
            int row = tid >> 4, cc = tid & 15;
            st0 += (tr0.x + tr0.y) + (tr0.z + tr0.w);
            uint2 w = {packbf(tr0.x, tr0.y), packbf(tr0.z, tr0.w)};
            *(uint2*)(&tbf[buf][sw128((uint32_t)(row * 128 + cc * 8))]) = w;
            if (tid < 64) {
                st1 += (tr1.x + tr1.y) + (tr1.z + tr1.w);
                uint2 w2 = {packbf(tr1.x, tr1.y), packbf(tr1.z, tr1.w)};
                *(uint2*)(&tbf[buf][sw128((uint32_t)((16 + row) * 128 + cc * 8))]) = w2;
            }
        }
        // Issue loads for chunk ch+1 (latency hidden behind sync + MMA)
        if (ch + 1 < cend) {
            const int c1 = (ch + 1) * KCH;
#pragma unroll
            for (int k = 0; k < 7; k++) {
                int j = tid + k * TPB;
                if (j < 1600) {
                    int row = j >> 4, cc = j & 15;
                    pr[k] = __ldcs((const float4*)(pmb + (size_t)row * Lc + c1) + cc);
                }
            }
            int row = tid >> 4, cc = tid & 15;
            tr0 = __ldcs((const float4*)(gtb + (size_t)row * Lc + c1) + cc);
            if (tid < 64)
                tr1 = __ldcs((const float4*)(gtb + (size_t)(16 + row) * Lc + c1) + cc);
        }
        __syncthreads(); // bf16[buf] ready; also fences prior MMA reads of buf

        // Warp-level GEMM on bf16[buf]: 4 k16-steps
        const uint32_t pb = smem_u32(&pbf[buf][0]);
        const uint32_t tb = smem_u32(&tbf[buf][0]);
#pragma unroll
        for (int ks = 0; ks < 4; ks++) {
            const uint32_t kb = (uint32_t)ks * 32;
            uint32_t a[4], b0[2], b1[2], b2r[2];
            ldmx4(pb + a_base + ((a_kb + kb) ^ a_x), a[0], a[1], a[2], a[3]);
            ldmx4(tb + b01_base + ((b01_kb + kb) ^ b01_x), b0[0], b0[1], b1[0], b1[1]);
            ldmx2(tb + b2_base + ((b2_kb + kb) ^ b2_x), b2r[0], b2r[1]);
            mma16816(acc[0], a, b0[0], b0[1]);
            mma16816(acc[1], a, b1[0], b1[1]);
            mma16816(acc[2], a, b2r[0], b2r[1]);
        }
    }

    // ---- Epilogue: pt via atomics; sp/st via per-z partial stores ----
    {
        const int gr = lane >> 2, qc = lane & 3;
        const int r0 = 16 * wid + gr, r1 = r0 + 8;
#pragma unroll
        for (int j = 0; j < 3; j++) {
            int col = 8 * j + 2 * qc;
            if (col + 1 < Mc) {
                if (r0 < Nc) {
                    atomicAdd(&g_pt[(b * Nc + r0) * Mc + col], acc[j][0]);
                    atomicAdd(&g_pt[(b * Nc + r0) * Mc + col + 1], acc[j][1]);
                }
                if (r1 < Nc) {
                    atomicAdd(&g_pt[(b * Nc + r1) * Mc + col], acc[j][2]);
                    atomicAdd(&g_pt[(b * Nc + r1) * Mc + col + 1], acc[j][3]);
                }
            }
        }
    }
    // sp: 16-lane groups share a p-row; plain store to this block's z-slot
#pragma unroll
    for (int k = 0; k < 7; k++) {
        float v = sp_loc[k];
#pragma unroll
        for (int o = 8; o; o >>= 1) v += __shfl_down_sync(0xffffffffu, v, o, 16);
        int row = (tid + k * TPB) >> 4;
        if ((lane & 15) == 0 && row < Nc)
            g_sp_part[(z * Bc + b) * Nc + row] = v;
    }
    // st
    {
        float v = st0;
#pragma unroll
        for (int o = 8; o; o >>= 1) v += __shfl_down_sync(0xffffffffu, v, o, 16);
        if ((lane & 15) == 0) g_st_part[(z * Bc + b) * Mc + (tid >> 4)] = v;
        float u = st1;
#pragma unroll
        for (int o = 8; o; o >>= 1) u += __shfl_down_sync(0xffffffffu, u, o, 16);
        if ((lane & 15) == 0 && tid < 64)
            g_st_part[(z * Bc + b) * Mc + 16 + (tid >> 4)] = u;
    }
}

// Combine. Block = 10 complete n-groups (200 outputs) within one batch b.
// Phase 1: reduce sp (10 rows) + st (20) over 74 z partials; all threads
// execute the shfl (full-warp participation), guards only on loads/writes.
// Phase 2: compute outputs; consume-and-clear g_pt for the next replay.
// gt_labels is int32 (JAX x64-disabled); clamp so bad labels can't trap.
__global__ void combine_kernel(const float* __restrict__ logits,
                               const int* __restrict__ labels,
                               float* __restrict__ out) {
    __shared__ float s_sp[10];
    __shared__ float s_st[Mc];
    const int tid = threadIdx.x;
    const int g0 = blockIdx.x * 10;
    const int b = g0 / Nc, n0 = g0 % Nc;

    // Phase 1: 32 keys (30 real), 8 threads/key, each covering z = sub+8i < 74.
    {
        const int key = tid >> 3, sub = tid & 7;
        float s = 0.f;
        if (key < 10) {
#pragma unroll
            for (int i = 0; i < 10; i++) {
                int zz = sub + 8 * i;
                if (zz < ZB) s += g_sp_part[(zz * Bc + b) * Nc + n0 + key];
            }
        } else if (key < 30) {
#pragma unroll
            for (int i = 0; i < 10; i++) {
                int zz = sub + 8 * i;
                if (zz < ZB) s += g_st_part[(zz * Bc + b) * Mc + (key - 10)];
            }
        }
#pragma unroll
        for (int o2 = 4; o2; o2 >>= 1) s += __shfl_down_sync(0xffffffffu, s, o2, 8);
        if (sub == 0 && key < 30) {
            if (key < 10) s_sp[key] = s;
            else s_st[key - 10] = s;
        }
    }
    __syncthreads();

    // Phase 2: 200 outputs
    if (tid < 200) {
        const int o = g0 * Mc + tid;
        const int m = tid % Mc, ng = tid / Mc;
        float pt = g_pt[o];
        g_pt[o] = 0.f; // clear for next replay (single reader per element)
        float sp = s_sp[ng];
        float st = s_st[m];
        int lab = labels[b * Mc + m];
        lab = lab < 0 ? 0 : (lab >= Cc ? Cc - 1 : lab);
        float logit = logits[(b * Nc + n0 + ng) * Cc + lab];

        const float invL = 1.0f / (float)Lc;
        float cost_class = -logit;
        float cost_mask = -(2.0f * pt + (float)Lc - sp - st) * invL;
        float cost_dice = 1.0f - (2.0f * pt + 1.0f) / (sp + st + 1.0f);
        out[o] = cost_class + cost_mask + cost_dice;
    }
}

extern "C" void kernel_launch(void* const* d_in, const int* in_sizes, int n_in,
                              void* d_out, int out_size) {
    const float* pred_logits = (const float*)d_in[0]; // (4,100,81) f32
    const float* pred_masks = (const float*)d_in[1];  // (4,100,256,256) f32
    const int* gt_labels = (const int*)d_in[2];       // (4,20) int32
    const float* gt_masks = (const float*)d_in[3];    // (4,20,256,256) f32
    float* out = (float*)d_out;                       // (4,100,20) f32

    dim3 grid(ZB, Bc); // 296 blocks = exactly 148 SMs x 2 CTAs
    main_kernel<<<grid, TPB>>>(pred_masks, gt_masks);
    combine_kernel<<<Bc * Nc / 10, 256>>>(pred_logits, gt_labels, out);
}